// round 8
// baseline (speedup 1.0000x reference)
#include <cuda_runtime.h>
#include <math.h>

#define NSTEPS 130
#define NLUT   27
#define ROWS   32
#define UROWS  132          // 130 data rows + 2 padding rows for tail prefetch

// srcA[l] / srcB[l]: flat-state index feeding mux selects A / B of LUT-lane l.
// Lanes 27..31 are constant-carrier lanes (self-wired).
__device__ __constant__ int c_srcA[32] = {
    1, 3, 3,   7, 0, 0,   4, 6, 6,   19, 12, 12,  16, 9, 9,
    13, 15, 15, 10, 18, 18, 22, 6, 6, 25, 15, 15,
    27, 28, 29, 30, 31};
__device__ __constant__ int c_srcB[32] = {
    17, 17, 1,  5, 5, 7,   11, 11, 4, 8, 8, 19,   28, 28, 16,
    2, 2, 13,   27, 27, 10, 23, 23, 22, 26, 26, 25,
    27, 28, 29, 30, 31};

#define BAR_ARRIVE(b, n) asm volatile("bar.arrive %0, %1;" :: "r"(b), "n"(n) : "memory")
#define BAR_WAIT(b, n)   asm volatile("bar.sync %0, %1;"   :: "r"(b), "n"(n) : "memory")

// Generic LUT eval: out = B*(A*u+v) + (A*r+s), quadruple q = (u,v,r,s)
#define LUT(A, B, q) fmaf((B), fmaf((A), (q).x, (q).y), fmaf((A), (q).z, (q).w))

__global__ void one_layer_net_kernel(const float* __restrict__ x,
                                     const float* __restrict__ weights,
                                     const float4* __restrict__ noise4,
                                     float* __restrict__ out) {
    extern __shared__ float4 s_uvrs[];   // [132][32] quadruples

    const int tid  = threadIdx.x;
    const int wrp  = tid >> 5;
    const int lane = tid & 31;

    if (wrp > 0) {
        // ------------------- PRODUCER WARPS (1..7) -------------------------
        const bool act = (lane < NLUT);
        const int  nl  = act ? lane : 0;

        // warp1 -> rows 0..5 (first block: iter0 needs rows<=5), warps 2..7
        // -> 20 rows each (6..125), warp1 pass 2 -> rows 126..129 + 2 pads.
        const int s0 = (wrp == 1) ? 0 : 6 + 20 * (wrp - 2);
        const int nrows = (wrp == 1) ? 6 : 20;

        // Front-batch noise loads (max MLP) BEFORE the weights load.
        float4 nbuf[20];
#pragma unroll
        for (int i = 0; i < 20; ++i)
            if (i < nrows) nbuf[i] = noise4[(s0 + i) * NLUT + nl];

        float4 wb = make_float4(0.f, 0.f, 0.f, 0.f);
        if (act) wb = reinterpret_cast<const float4*>(weights)[lane];
        const float c0 = fabsf(1.0f - fabsf(wb.x)) * 0.125f;
        const float c1 = fabsf(1.0f - fabsf(wb.y)) * 0.125f;
        const float c2 = fabsf(1.0f - fabsf(wb.z)) * 0.125f;
        const float c3 = fabsf(1.0f - fabsf(wb.w)) * 0.125f;
        const float xv = (lane == 27) ? x[0] : ((lane == 28) ? x[1] : 0.0f);

#pragma unroll
        for (int i = 0; i < 20; ++i) {
            if (i >= nrows) break;
            const float4 n = nbuf[i];
            const float w0 = fmaf(c0, n.x, wb.x);
            const float w1 = fmaf(c1, n.y, wb.y);
            const float w2 = fmaf(c2, n.z, wb.z);
            const float w3 = fmaf(c3, n.w, wb.w);
            const float d01 = w1 - w0, d23 = w3 - w2;
            const float p01 = w0 + w1, p23 = w2 + w3;
            float4 q;
            q.x = act ? 0.25f * (d23 - d01) : 0.f;
            q.y = act ? 0.25f * (p23 - p01) : 0.f;
            q.z = act ? 0.25f * (d01 + d23) : 0.f;
            q.w = act ? 0.25f * (p01 + p23) : xv;
            s_uvrs[(s0 + i) * ROWS + lane] = q;
        }
        // warps 1..4: individual 64-thread barriers; warps 5..7 share bar 5.
        if (wrp <= 4) { BAR_ARRIVE(wrp, 64); }
        else          { int b5 = 5; BAR_ARRIVE(b5, 128); }

        if (wrp == 1) {
            // Second pass: rows 126..129 real, 130..131 zero padding.
            float4 nb2[4];
#pragma unroll
            for (int i = 0; i < 4; ++i)
                nb2[i] = noise4[(126 + i) * NLUT + nl];
#pragma unroll
            for (int i = 0; i < 4; ++i) {
                const float4 n = nb2[i];
                const float w0 = fmaf(c0, n.x, wb.x);
                const float w1 = fmaf(c1, n.y, wb.y);
                const float w2 = fmaf(c2, n.z, wb.z);
                const float w3 = fmaf(c3, n.w, wb.w);
                const float d01 = w1 - w0, d23 = w3 - w2;
                const float p01 = w0 + w1, p23 = w2 + w3;
                float4 q;
                q.x = act ? 0.25f * (d23 - d01) : 0.f;
                q.y = act ? 0.25f * (p23 - p01) : 0.f;
                q.z = act ? 0.25f * (d01 + d23) : 0.f;
                q.w = act ? 0.25f * (p01 + p23) : xv;
                s_uvrs[(126 + i) * ROWS + lane] = q;
            }
            s_uvrs[130 * ROWS + lane] = make_float4(0.f, 0.f, 0.f, 0.f);
            s_uvrs[131 * ROWS + lane] = make_float4(0.f, 0.f, 0.f, 0.f);
            int b8 = 8;
            BAR_ARRIVE(b8, 64);
        }
        return;
    }

    // ----------------------- CONSUMER WARP (0) -----------------------------
    // 3-step fusion. Per iter (steps 3k..3k+2), lane l evaluates:
    //   mids  M_aa,M_ba,M_ab,M_bb : LUTs of lanes aa,ba,ab,bb at row 3k
    //   iA = LUT_sa(M_aa, M_ba) at row 3k+1 ; iB = LUT_sb(M_ab, M_bb)
    //   state' = LUT_l(iA, iB) at row 3k+2
    const int sa = c_srcA[lane], sb = c_srcB[lane];
    const int aa = c_srcA[sa],  ba = c_srcB[sa];
    const int ab = c_srcA[sb],  bb = c_srcB[sb];
    const int q1 = c_srcA[aa],  q2 = c_srcB[aa];
    const int q3 = c_srcA[ba],  q4 = c_srcB[ba];
    const int q5 = c_srcA[ab],  q6 = c_srcB[ab];
    const int q7 = c_srcA[bb],  q8 = c_srcB[bb];

    float state = (lane < NLUT) ? -1.0f
                : (lane == 27) ? x[0]
                : (lane == 28) ? x[1] : 0.0f;

    int b = 1;
    BAR_WAIT(b, 64);   // rows 0..5 ready

    const float4* p0A = s_uvrs + 0 * ROWS + aa;
    const float4* p0B = s_uvrs + 0 * ROWS + ba;
    const float4* p0C = s_uvrs + 0 * ROWS + ab;
    const float4* p0D = s_uvrs + 0 * ROWS + bb;
    const float4* p1A = s_uvrs + 1 * ROWS + sa;
    const float4* p1B = s_uvrs + 1 * ROWS + sb;
    const float4* p2  = s_uvrs + 2 * ROWS + lane;

    float4 c0A = p0A[0], c0B = p0B[0], c0C = p0C[0], c0D = p0D[0];
    float4 c1A = p1A[0], c1B = p1B[0], c2q = p2[0];
    p0A += 3 * ROWS; p0B += 3 * ROWS; p0C += 3 * ROWS; p0D += 3 * ROWS;
    p1A += 3 * ROWS; p1B += 3 * ROWS; p2  += 3 * ROWS;

#define SCAN3()                                                              \
    do {                                                                     \
        const float4 n0A = p0A[0], n0B = p0B[0], n0C = p0C[0], n0D = p0D[0]; \
        const float4 n1A = p1A[0], n1B = p1B[0], n2q = p2[0];                \
        p0A += 3 * ROWS; p0B += 3 * ROWS; p0C += 3 * ROWS; p0D += 3 * ROWS;  \
        p1A += 3 * ROWS; p1B += 3 * ROWS; p2  += 3 * ROWS;                   \
        const float v1 = __shfl_sync(0xFFFFFFFFu, state, q1);                \
        const float v2 = __shfl_sync(0xFFFFFFFFu, state, q2);                \
        const float v3 = __shfl_sync(0xFFFFFFFFu, state, q3);                \
        const float v4 = __shfl_sync(0xFFFFFFFFu, state, q4);                \
        const float v5 = __shfl_sync(0xFFFFFFFFu, state, q5);                \
        const float v6 = __shfl_sync(0xFFFFFFFFu, state, q6);                \
        const float v7 = __shfl_sync(0xFFFFFFFFu, state, q7);                \
        const float v8 = __shfl_sync(0xFFFFFFFFu, state, q8);                \
        const float Maa = LUT(v1, v2, c0A);                                  \
        const float Mba = LUT(v3, v4, c0B);                                  \
        const float Mab = LUT(v5, v6, c0C);                                  \
        const float Mbb = LUT(v7, v8, c0D);                                  \
        const float iA  = LUT(Maa, Mba, c1A);                                \
        const float iB  = LUT(Mab, Mbb, c1B);                                \
        state = LUT(iA, iB, c2q);                                            \
        c0A = n0A; c0B = n0B; c0C = n0C; c0D = n0D;                          \
        c1A = n1A; c1B = n1B; c2q = n2q;                                     \
    } while (0)

    // iter k consumes rows 3k..3k+2, prefetches rows 3k+3..3k+5:
    //   k=0      needs <=5    (bar1, passed)
    //   k=1..6   needs <=23   (bar2)      k=7..13  needs <=44  (bar3)
    //   k=14..20 needs <=65   (bar4)      k=21..40 needs <=125 (bar5, merged)
    //   k=41..42 needs <=131  (bar8)
    SCAN3();
    b = 2; BAR_WAIT(b, 64);
#pragma unroll
    for (int i = 0; i < 6; ++i) SCAN3();
    b = 3; BAR_WAIT(b, 64);
#pragma unroll
    for (int i = 0; i < 7; ++i) SCAN3();
    b = 4; BAR_WAIT(b, 64);
#pragma unroll
    for (int i = 0; i < 7; ++i) SCAN3();
    b = 5; BAR_WAIT(b, 128);
#pragma unroll
    for (int i = 0; i < 20; ++i) SCAN3();
    b = 8; BAR_WAIT(b, 64);
    // Preload the final single-step quadruple (row 129, own lane) early.
    const float4 fq = s_uvrs[129 * ROWS + lane];
    SCAN3();
    SCAN3();                 // after this: state = state_129

    // Final single step 129 -> 130.
    {
        const float A = __shfl_sync(0xFFFFFFFFu, state, sa);
        const float B = __shfl_sync(0xFFFFFFFFu, state, sb);
        state = LUT(A, B, fq);
    }

    // Outputs: final[0,1] -> flat 1, final[1,2] -> flat 5, final[7,2] -> flat 23.
    if (lane == 1)  out[0] = state;
    if (lane == 5)  out[1] = state;
    if (lane == 23) out[2] = state;
}

extern "C" void kernel_launch(void* const* d_in, const int* in_sizes, int n_in,
                              void* d_out, int out_size) {
    (void)in_sizes; (void)n_in; (void)out_size;
    const float*  x  = (const float*)d_in[0];      // [2]
    const float*  w  = (const float*)d_in[1];      // [9,3,4]
    const float4* nz = (const float4*)d_in[2];     // [130,9,3,4] as float4
    float* out = (float*)d_out;                    // [3]

    const size_t smem = (size_t)UROWS * ROWS * sizeof(float4);   // 67584 B
    cudaFuncSetAttribute(one_layer_net_kernel,
                         cudaFuncAttributeMaxDynamicSharedMemorySize, (int)smem);
    one_layer_net_kernel<<<1, 256, smem>>>(x, w, nz, out);
}